// round 1
// baseline (speedup 1.0000x reference)
#include <cuda_runtime.h>
#include <math.h>

// Problem constants
#define BV 2
#define TV 1536
#define DV 1024
#define HH 16
#define HD 64
#define SS 3072            // B*T
#define D3 3072            // 3*D

// Scratch (device globals: allocation-free per harness rules)
__device__ float g_qkv[(size_t)SS * D3];            // 37.7 MB  [s, c*D + h*64 + d]
__device__ float g_scores[(size_t)HH * SS * SS];    // 604 MB   [h, s, t]
__device__ float g_y[(size_t)SS * DV];              // 12.6 MB  [s, h*64 + d]

// ---------------------------------------------------------------------------
// Generic NT GEMM: C[m,n] = alpha * sum_k A[m,k] * W[n,k]  (+ bias[n])
// Both A and W row-major with reduction dim contiguous. 128x128 tile, BK=8,
// 256 threads, 8x8 per-thread register tile. All calls use M,N % 128 == 0 and
// K % 8 == 0 so no bounds checks are needed.
// PERM_A: read A row m from physical row (m % TV)*BV + (m / TV)   (the
// reference's mismatched unflatten folded into the final projection).
// ---------------------------------------------------------------------------
template <bool PERM_A>
__global__ __launch_bounds__(256)
void gemm_nt(const float* __restrict__ A, int lda,
             const float* __restrict__ W, int ldw,
             const float* __restrict__ bias,
             float* __restrict__ C, int ldc,
             int K, float alpha,
             long long aBatch, long long wBatch, long long cBatch)
{
    const int bm = blockIdx.y * 128;
    const int bn = blockIdx.x * 128;
    const int z  = blockIdx.z;
    A += (size_t)z * aBatch;
    W += (size_t)z * wBatch;
    C += (size_t)z * cBatch;

    __shared__ float As[8][128];
    __shared__ float Ws[8][128];

    const int tid = threadIdx.x;
    const int tx  = tid & 15;        // 0..15  -> 8 output cols
    const int ty  = tid >> 4;        // 0..15  -> 8 output rows

    // loader mapping: each thread loads one float4 of A and one of W per k-tile
    const int lr = tid >> 1;         // tile row 0..127
    const int lk = (tid & 1) * 4;    // k offset 0 or 4

    int arow = bm + lr;
    if (PERM_A) arow = (arow % TV) * BV + (arow / TV);
    const float* aptr = A + (size_t)arow * lda + lk;
    const float* wptr = W + (size_t)(bn + lr) * ldw + lk;

    float acc[8][8];
#pragma unroll
    for (int i = 0; i < 8; i++)
#pragma unroll
        for (int j = 0; j < 8; j++) acc[i][j] = 0.f;

    for (int k0 = 0; k0 < K; k0 += 8) {
        float4 av = *(const float4*)(aptr + k0);
        float4 wv = *(const float4*)(wptr + k0);
        As[lk + 0][lr] = av.x; As[lk + 1][lr] = av.y;
        As[lk + 2][lr] = av.z; As[lk + 3][lr] = av.w;
        Ws[lk + 0][lr] = wv.x; Ws[lk + 1][lr] = wv.y;
        Ws[lk + 2][lr] = wv.z; Ws[lk + 3][lr] = wv.w;
        __syncthreads();

#pragma unroll
        for (int k = 0; k < 8; k++) {
            float ra[8], rw[8];
#pragma unroll
            for (int i = 0; i < 8; i++) ra[i] = As[k][ty * 8 + i];
#pragma unroll
            for (int j = 0; j < 8; j++) rw[j] = Ws[k][tx * 8 + j];
#pragma unroll
            for (int i = 0; i < 8; i++)
#pragma unroll
                for (int j = 0; j < 8; j++) acc[i][j] += ra[i] * rw[j];
        }
        __syncthreads();
    }

    // epilogue: two float4 stores per output row
#pragma unroll
    for (int i = 0; i < 8; i++) {
        const int m = bm + ty * 8 + i;
        const int n = bn + tx * 8;
        float out[8];
#pragma unroll
        for (int j = 0; j < 8; j++) {
            float v = alpha * acc[i][j];
            if (bias) v += bias[n + j];
            out[j] = v;
        }
        float* cp = C + (size_t)m * ldc + n;
        *(float4*)(cp + 0) = make_float4(out[0], out[1], out[2], out[3]);
        *(float4*)(cp + 4) = make_float4(out[4], out[5], out[6], out[7]);
    }
}

// ---------------------------------------------------------------------------
// Row softmax over g_scores: H*S rows of length S. One block (256 thr) / row;
// each thread holds 12 elements in registers (S = 3072 = 256*12).
// ---------------------------------------------------------------------------
__global__ __launch_bounds__(256)
void softmax_rows(float* __restrict__ scores)
{
    float* p = scores + (size_t)blockIdx.x * SS;
    const int tid  = threadIdx.x;
    const int lane = tid & 31;
    const int wid  = tid >> 5;
    __shared__ float red[8];

    float v[12];
    float mx = -1e30f;
#pragma unroll
    for (int i = 0; i < 12; i++) {
        v[i] = p[tid + i * 256];
        mx = fmaxf(mx, v[i]);
    }
#pragma unroll
    for (int o = 16; o > 0; o >>= 1) mx = fmaxf(mx, __shfl_xor_sync(~0u, mx, o));
    if (lane == 0) red[wid] = mx;
    __syncthreads();
    mx = red[0];
#pragma unroll
    for (int w = 1; w < 8; w++) mx = fmaxf(mx, red[w]);
    __syncthreads();

    float sum = 0.f;
#pragma unroll
    for (int i = 0; i < 12; i++) {
        v[i] = __expf(v[i] - mx);
        sum += v[i];
    }
#pragma unroll
    for (int o = 16; o > 0; o >>= 1) sum += __shfl_xor_sync(~0u, sum, o);
    if (lane == 0) red[wid] = sum;
    __syncthreads();
    sum = red[0];
#pragma unroll
    for (int w = 1; w < 8; w++) sum += red[w];

    const float inv = 1.0f / sum;
#pragma unroll
    for (int i = 0; i < 12; i++) p[tid + i * 256] = v[i] * inv;
}

// ---------------------------------------------------------------------------
// AV GEMM (NN, narrow N): y[s, h*64+d] = sum_t attn[h,s,t] * v[t, h*64+d]
// Tile: 128 (rows) x 64 (full head dim), BK=16. 256 threads, 8x4 per thread.
// grid = (S/128, H)
// ---------------------------------------------------------------------------
__global__ __launch_bounds__(256)
void av_gemm(const float* __restrict__ scores,
             const float* __restrict__ qkv,
             float* __restrict__ y)
{
    const int h  = blockIdx.y;
    const int bm = blockIdx.x * 128;
    const float* A = scores + (size_t)h * SS * SS;
    const float* V = qkv + 2 * DV + h * HD;   // row stride D3

    __shared__ float As[16][128];
    __shared__ float Vs[16][64];

    const int tid = threadIdx.x;
    const int tx  = tid & 15;      // -> 4 cols of head dim
    const int ty  = tid >> 4;      // -> 8 rows

    float acc[8][4];
#pragma unroll
    for (int i = 0; i < 8; i++)
#pragma unroll
        for (int j = 0; j < 4; j++) acc[i][j] = 0.f;

    for (int k0 = 0; k0 < SS; k0 += 16) {
        // load attn tile 128x16 (512 float4, 2 per thread), store transposed
#pragma unroll
        for (int it = 0; it < 2; it++) {
            const int idx = tid + it * 256;
            const int r = idx >> 2;
            const int c = (idx & 3) * 4;
            float4 a = *(const float4*)(A + (size_t)(bm + r) * SS + k0 + c);
            As[c + 0][r] = a.x; As[c + 1][r] = a.y;
            As[c + 2][r] = a.z; As[c + 3][r] = a.w;
        }
        // load V tile 16x64 (256 float4, 1 per thread)
        {
            const int r = tid >> 4;
            const int c = (tid & 15) * 4;
            float4 vv = *(const float4*)(V + (size_t)(k0 + r) * D3 + c);
            *(float4*)&Vs[r][c] = vv;
        }
        __syncthreads();

#pragma unroll
        for (int k = 0; k < 16; k++) {
            float ra[8], rv[4];
#pragma unroll
            for (int i = 0; i < 8; i++) ra[i] = As[k][ty * 8 + i];
#pragma unroll
            for (int j = 0; j < 4; j++) rv[j] = Vs[k][tx * 4 + j];
#pragma unroll
            for (int i = 0; i < 8; i++)
#pragma unroll
                for (int j = 0; j < 4; j++) acc[i][j] += ra[i] * rv[j];
        }
        __syncthreads();
    }

#pragma unroll
    for (int i = 0; i < 8; i++) {
        float* yp = y + (size_t)(bm + ty * 8 + i) * DV + h * HD + tx * 4;
        *(float4*)yp = make_float4(acc[i][0], acc[i][1], acc[i][2], acc[i][3]);
    }
}

// ---------------------------------------------------------------------------
extern "C" void kernel_launch(void* const* d_in, const int* in_sizes, int n_in,
                              void* d_out, int out_size)
{
    const float* x    = (const float*)d_in[0];   // (B,T,D)  -> [S, D]
    const float* Wqkv = (const float*)d_in[1];   // (3D, D)
    const float* bqkv = (const float*)d_in[2];   // (3D)
    const float* Wout = (const float*)d_in[3];   // (D, D)
    const float* bout = (const float*)d_in[4];   // (D)
    float* out = (float*)d_out;                  // (B,T,D)

    float* qkv;    cudaGetSymbolAddress((void**)&qkv,    g_qkv);
    float* scores; cudaGetSymbolAddress((void**)&scores, g_scores);
    float* y;      cudaGetSymbolAddress((void**)&y,      g_y);

    dim3 blk(256);

    // 1) qkv = x @ Wqkv^T + bqkv        [S, 3D]
    gemm_nt<false><<<dim3(D3 / 128, SS / 128, 1), blk>>>(
        x, DV, Wqkv, DV, bqkv, qkv, D3, DV, 1.0f, 0, 0, 0);

    // 2) scores[h] = (Q_h @ K_h^T) / 8  [H, S, S]
    gemm_nt<false><<<dim3(SS / 128, SS / 128, HH), blk>>>(
        qkv /*Q base*/, D3, qkv + DV /*K base*/, D3, nullptr,
        scores, SS, HD, 0.125f,
        /*aBatch=*/HD, /*wBatch=*/HD, /*cBatch=*/(long long)SS * SS);

    // 3) softmax over last dim
    softmax_rows<<<HH * SS, blk>>>(scores);

    // 4) y = attn @ V                   [S, D]
    av_gemm<<<dim3(SS / 128, HH), blk>>>(scores, qkv, y);

    // 5) out[b*T+t] = y[t*B+b] @ Wout^T + bout   (mismatched unflatten folded in)
    gemm_nt<true><<<dim3(DV / 128, SS / 128, 1), blk>>>(
        y, DV, Wout, DV, bout, out, DV, DV, 1.0f, 0, 0, 0);
}

// round 3
// speedup vs baseline: 1.7616x; 1.7616x over previous
#include <cuda_runtime.h>
#include <cuda_bf16.h>
#include <stdint.h>

// Problem constants
#define BV 2
#define TV 1536
#define DV 1024
#define HH 16
#define HD 64
#define SS 3072            // B*T
#define D3 3072            // 3*D

// Scratch (device globals: allocation-free per harness rules)
__device__ float g_qkv[(size_t)SS * D3];            // 37.7 MB
__device__ float g_scores[(size_t)HH * SS * SS];    // 604 MB
__device__ float g_y[(size_t)SS * DV];              // 12.6 MB

#define KC  32             // k-chunk (bf16 elems)
#define ST  40             // smem row stride in halves (32 + 8 pad -> conflict-free ldmatrix)
#define ST2 80             // ... in bytes

// ---------------------------------------------------------------------------
__device__ __forceinline__ uint32_t smem_u32(const void* p) {
    uint32_t a;
    asm("{ .reg .u64 t; cvta.to.shared.u64 t, %1; cvt.u32.u64 %0, t; }"
        : "=r"(a) : "l"(p));
    return a;
}
__device__ __forceinline__ void ldsm4(uint32_t r[4], uint32_t addr) {
    asm volatile("ldmatrix.sync.aligned.m8n8.x4.shared.b16 {%0,%1,%2,%3}, [%4];"
                 : "=r"(r[0]), "=r"(r[1]), "=r"(r[2]), "=r"(r[3]) : "r"(addr));
}
__device__ __forceinline__ void mma16816(float c[4], const uint32_t a[4],
                                         uint32_t b0, uint32_t b1) {
    asm volatile("mma.sync.aligned.m16n8k16.row.col.f32.bf16.bf16.f32 "
                 "{%0,%1,%2,%3}, {%4,%5,%6,%7}, {%8,%9}, {%0,%1,%2,%3};"
                 : "+f"(c[0]), "+f"(c[1]), "+f"(c[2]), "+f"(c[3])
                 : "r"(a[0]), "r"(a[1]), "r"(a[2]), "r"(a[3]), "r"(b0), "r"(b1));
}
// split fp32x4 -> bf16 hi/lo, store packed (8B each) at half-offset hoff
__device__ __forceinline__ void split4(char* hi, char* lo, int hoff, float4 v) {
    __nv_bfloat162 h01 = __floats2bfloat162_rn(v.x, v.y);
    __nv_bfloat162 h23 = __floats2bfloat162_rn(v.z, v.w);
    __nv_bfloat162 l01 = __floats2bfloat162_rn(v.x - __bfloat162float(h01.x),
                                               v.y - __bfloat162float(h01.y));
    __nv_bfloat162 l23 = __floats2bfloat162_rn(v.z - __bfloat162float(h23.x),
                                               v.w - __bfloat162float(h23.y));
    *(uint2*)(hi + hoff * 2) = make_uint2(*(uint32_t*)&h01, *(uint32_t*)&h23);
    *(uint2*)(lo + hoff * 2) = make_uint2(*(uint32_t*)&l01, *(uint32_t*)&l23);
}

// ===========================================================================
// HMMA (mma.sync bf16, split-fp32) GEMM:
//   C[m,n] = alpha * sum_k A[m,k] * B[n,k]  (+ bias[n])
// Block tile 128 x NTILE, KC=32.  8 warps as 4(m) x 2(n): warp tile 32 x NTILE/2.
// PERM_A : A row m read from physical row (m % TV)*BV + (m / TV)
// TRANS_B: B source is [k, n] row-major (stride ldb); transposed while staging
// ===========================================================================
template <int NTILE, bool PERM_A, bool TRANS_B>
__global__ __launch_bounds__(256, 1)
void mma_gemm(const float* __restrict__ A, int lda,
              const float* __restrict__ Bm, int ldb,
              const float* __restrict__ bias,
              float* __restrict__ C, int ldc,
              int K, float alpha,
              long long aB, long long bB, long long cB)
{
    extern __shared__ char smem[];
    constexpr int NBW    = NTILE / 16;              // n8-blocks per warp
    constexpr int ABYTES = 128 * ST2;               // one bf16 matrix tile
    constexpr int BBYTES = NTILE * ST2;
    constexpr int BUFB   = 2 * ABYTES + 2 * BBYTES; // Ah,Al,Bh,Bl
    constexpr int BITERS = TRANS_B ? 2 : NTILE / 32;

    const int tid  = threadIdx.x;
    const int lane = tid & 31;
    const int wid  = tid >> 5;
    const int wm   = (wid & 3) * 32;                // warp row base in tile
    const int wn   = (wid >> 2) * (NTILE / 2);      // warp col base in tile

    const int bm = blockIdx.y * 128;
    const int bn = blockIdx.x * NTILE;
    A  += (size_t)blockIdx.z * aB;
    Bm += (size_t)blockIdx.z * bB;
    C  += (size_t)blockIdx.z * cB;

    const uint32_t sb0 = smem_u32(smem);

    // ---- global load pointers (A: 4 iters of 128B-coalesced float4) ----
    const int c4 = (tid & 7) * 4;
    const float* aPtr[4];
#pragma unroll
    for (int it = 0; it < 4; it++) {
        int r = bm + (tid >> 3) + it * 32;
        if (PERM_A) r = (r % TV) * BV + (r / TV);
        aPtr[it] = A + (size_t)r * lda + c4;
    }
    const float* bPtr[BITERS];
#pragma unroll
    for (int it = 0; it < BITERS; it++) {
        if (!TRANS_B)
            bPtr[it] = Bm + (size_t)(bn + (tid >> 3) + it * 32) * ldb + c4;
        else
            bPtr[it] = Bm + (size_t)((tid >> 4) + it * 16) * ldb + bn + (tid & 15) * 4;
    }

    float acc[2][NBW][4];
#pragma unroll
    for (int i = 0; i < 2; i++)
#pragma unroll
        for (int j = 0; j < NBW; j++)
#pragma unroll
            for (int q = 0; q < 4; q++) acc[i][j][q] = 0.f;

    const int nc = K / KC;
    float4 pfA[4], pfB[BITERS];

    // ---- prologue: fetch + stage chunk 0 ----
#pragma unroll
    for (int it = 0; it < 4; it++) pfA[it] = *(const float4*)(aPtr[it]);
#pragma unroll
    for (int it = 0; it < BITERS; it++) pfB[it] = *(const float4*)(bPtr[it]);
    {
        char* base = smem;
        char* Ah = base;            char* Al = base + ABYTES;
        char* Bh = base + 2*ABYTES; char* Bl = Bh + BBYTES;
#pragma unroll
        for (int it = 0; it < 4; it++)
            split4(Ah, Al, ((tid >> 3) + it * 32) * ST + c4, pfA[it]);
        if (!TRANS_B) {
#pragma unroll
            for (int it = 0; it < BITERS; it++)
                split4(Bh, Bl, ((tid >> 3) + it * 32) * ST + c4, pfB[it]);
        } else {
#pragma unroll
            for (int it = 0; it < BITERS; it++) {
                int kr = (tid >> 4) + it * 16, n4 = (tid & 15) * 4;
                float vv[4] = {pfB[it].x, pfB[it].y, pfB[it].z, pfB[it].w};
#pragma unroll
                for (int j = 0; j < 4; j++) {
                    __nv_bfloat16 h = __float2bfloat16_rn(vv[j]);
                    __nv_bfloat16 l = __float2bfloat16_rn(vv[j] - __bfloat162float(h));
                    int off = ((n4 + j) * ST + kr) * 2;
                    *(__nv_bfloat16*)(Bh + off) = h;
                    *(__nv_bfloat16*)(Bl + off) = l;
                }
            }
        }
    }
    __syncthreads();

    // ---- main loop ----
    for (int ci = 0; ci < nc; ci++) {
        const bool more = (ci + 1 < nc);
        if (more) {
            const int k0 = (ci + 1) * KC;
#pragma unroll
            for (int it = 0; it < 4; it++) pfA[it] = *(const float4*)(aPtr[it] + k0);
#pragma unroll
            for (int it = 0; it < BITERS; it++)
                pfB[it] = *(const float4*)(bPtr[it] + (TRANS_B ? (size_t)k0 * ldb : (size_t)k0));
        }

        // compute on buffer ci&1
        {
            const uint32_t sb  = sb0 + (ci & 1) * BUFB;
            const uint32_t sAh = sb, sAl = sb + ABYTES;
            const uint32_t sBh = sb + 2 * ABYTES, sBl = sBh + BBYTES;
            const int arow = wm + (lane & 15);
            const int nrow0 = wn + (lane & 7) + ((lane >> 4) << 3);
            const int kbB = ((lane >> 3) & 1) * 8;
            const int kbA = (lane >> 4) * 8;
#pragma unroll
            for (int kk = 0; kk < KC; kk += 16) {
                uint32_t ah[2][4], al[2][4];
                const uint32_t aoff = arow * ST2 + (kk + kbA) * 2;
                ldsm4(ah[0], sAh + aoff);
                ldsm4(ah[1], sAh + aoff + 16 * ST2);
                ldsm4(al[0], sAl + aoff);
                ldsm4(al[1], sAl + aoff + 16 * ST2);
#pragma unroll
                for (int p = 0; p < NBW / 2; p++) {
                    uint32_t bh[4], bl[4];
                    const uint32_t boff = (nrow0 + p * 16) * ST2 + (kk + kbB) * 2;
                    ldsm4(bh, sBh + boff);
                    ldsm4(bl, sBl + boff);
#pragma unroll
                    for (int fm = 0; fm < 2; fm++) {
                        mma16816(acc[fm][2*p  ], ah[fm], bh[0], bh[1]);
                        mma16816(acc[fm][2*p  ], ah[fm], bl[0], bl[1]);
                        mma16816(acc[fm][2*p  ], al[fm], bh[0], bh[1]);
                        mma16816(acc[fm][2*p+1], ah[fm], bh[2], bh[3]);
                        mma16816(acc[fm][2*p+1], ah[fm], bl[2], bl[3]);
                        mma16816(acc[fm][2*p+1], al[fm], bh[2], bh[3]);
                    }
                }
            }
        }

        if (more) {
            char* base = smem + ((ci + 1) & 1) * BUFB;
            char* Ah = base;            char* Al = base + ABYTES;
            char* Bh = base + 2*ABYTES; char* Bl = Bh + BBYTES;
#pragma unroll
            for (int it = 0; it < 4; it++)
                split4(Ah, Al, ((tid >> 3) + it * 32) * ST + c4, pfA[it]);
            if (!TRANS_B) {
#pragma unroll
                for (int it = 0; it < BITERS; it++)
                    split4(Bh, Bl, ((tid >> 3) + it * 32) * ST + c4, pfB[it]);
            } else {
#pragma unroll
                for (int it = 0; it < BITERS; it++) {
                    int kr = (tid >> 4) + it * 16, n4 = (tid & 15) * 4;
                    float vv[4] = {pfB[it].x, pfB[it].y, pfB[it].z, pfB[it].w};
#pragma unroll
                    for (int j = 0; j < 4; j++) {
                        __nv_bfloat16 h = __float2bfloat16_rn(vv[j]);
                        __nv_bfloat16 l = __float2bfloat16_rn(vv[j] - __bfloat162float(h));
                        int off = ((n4 + j) * ST + kr) * 2;
                        *(__nv_bfloat16*)(Bh + off) = h;
                        *(__nv_bfloat16*)(Bl + off) = l;
                    }
                }
            }
        }
        __syncthreads();
    }

    // ---- epilogue ----
#pragma unroll
    for (int fm = 0; fm < 2; fm++) {
#pragma unroll
        for (int nb = 0; nb < NBW; nb++) {
            const int row = bm + wm + fm * 16 + (lane >> 2);
            const int col = bn + wn + nb * 8 + (lane & 3) * 2;
            float b0 = 0.f, b1 = 0.f;
            if (bias) { b0 = bias[col]; b1 = bias[col + 1]; }
            float2 v0 = make_float2(alpha * acc[fm][nb][0] + b0,
                                    alpha * acc[fm][nb][1] + b1);
            float2 v1 = make_float2(alpha * acc[fm][nb][2] + b0,
                                    alpha * acc[fm][nb][3] + b1);
            *(float2*)(C + (size_t)row * ldc + col)       = v0;
            *(float2*)(C + (size_t)(row + 8) * ldc + col) = v1;
        }
    }
}

// ---------------------------------------------------------------------------
// Row softmax: H*S rows of length S. One block (256 thr) per row.
// ---------------------------------------------------------------------------
__global__ __launch_bounds__(256)
void softmax_rows(float* __restrict__ scores)
{
    float* p = scores + (size_t)blockIdx.x * SS;
    const int tid  = threadIdx.x;
    const int lane = tid & 31;
    const int wid  = tid >> 5;
    __shared__ float red[8];

    float v[12];
    float mx = -1e30f;
#pragma unroll
    for (int i = 0; i < 12; i++) {
        v[i] = p[tid + i * 256];
        mx = fmaxf(mx, v[i]);
    }
#pragma unroll
    for (int o = 16; o > 0; o >>= 1) mx = fmaxf(mx, __shfl_xor_sync(~0u, mx, o));
    if (lane == 0) red[wid] = mx;
    __syncthreads();
    mx = red[0];
#pragma unroll
    for (int w = 1; w < 8; w++) mx = fmaxf(mx, red[w]);
    __syncthreads();

    float sum = 0.f;
#pragma unroll
    for (int i = 0; i < 12; i++) {
        v[i] = __expf(v[i] - mx);
        sum += v[i];
    }
#pragma unroll
    for (int o = 16; o > 0; o >>= 1) sum += __shfl_xor_sync(~0u, sum, o);
    if (lane == 0) red[wid] = sum;
    __syncthreads();
    sum = red[0];
#pragma unroll
    for (int w = 1; w < 8; w++) sum += red[w];

    const float inv = 1.0f / sum;
#pragma unroll
    for (int i = 0; i < 12; i++) p[tid + i * 256] = v[i] * inv;
}

// ---------------------------------------------------------------------------
extern "C" void kernel_launch(void* const* d_in, const int* in_sizes, int n_in,
                              void* d_out, int out_size)
{
    const float* x    = (const float*)d_in[0];   // (B,T,D)
    const float* Wqkv = (const float*)d_in[1];   // (3D, D)
    const float* bqkv = (const float*)d_in[2];   // (3D)
    const float* Wout = (const float*)d_in[3];   // (D, D)
    const float* bout = (const float*)d_in[4];   // (D)
    float* out = (float*)d_out;                  // (B,T,D)

    float* qkv;    cudaGetSymbolAddress((void**)&qkv,    g_qkv);
    float* scores; cudaGetSymbolAddress((void**)&scores, g_scores);
    float* y;      cudaGetSymbolAddress((void**)&y,      g_y);

    constexpr int AB = 128 * ST2;
    constexpr int SMEM128 = 2 * (2 * AB + 2 * 128 * ST2);  // 81920
    constexpr int SMEM64  = 2 * (2 * AB + 2 * 64 * ST2);   // 61440

    cudaFuncSetAttribute(mma_gemm<128, false, false>,
                         cudaFuncAttributeMaxDynamicSharedMemorySize, SMEM128);
    cudaFuncSetAttribute(mma_gemm<128, true, false>,
                         cudaFuncAttributeMaxDynamicSharedMemorySize, SMEM128);
    cudaFuncSetAttribute(mma_gemm<64, false, true>,
                         cudaFuncAttributeMaxDynamicSharedMemorySize, SMEM64);

    // 1) qkv = x @ Wqkv^T + bqkv                         [S, 3D]
    mma_gemm<128, false, false><<<dim3(D3 / 128, SS / 128, 1), 256, SMEM128>>>(
        x, DV, Wqkv, DV, bqkv, qkv, D3, DV, 1.0f, 0, 0, 0);

    // 2) scores[h] = (Q_h @ K_h^T) / 8                   [H, S, S]
    mma_gemm<128, false, false><<<dim3(SS / 128, SS / 128, HH), 256, SMEM128>>>(
        qkv, D3, qkv + DV, D3, nullptr, scores, SS, HD, 0.125f,
        (long long)HD, (long long)HD, (long long)SS * SS);

    // 3) softmax over last dim
    softmax_rows<<<HH * SS, 256>>>(scores);

    // 4) y[s, h*64+d] = sum_t attn[h,s,t] * V[t, h*64+d] [S, D]
    mma_gemm<64, false, true><<<dim3(1, SS / 128, HH), 256, SMEM64>>>(
        scores, SS, qkv + 2 * DV, D3, nullptr, y, DV, SS, 1.0f,
        (long long)SS * SS, (long long)HD, (long long)HD);

    // 5) out[b*T+t] = y[t*B+b] @ Wout^T + bout  (mismatched unflatten folded in)
    mma_gemm<128, true, false><<<dim3(DV / 128, SS / 128, 1), 256, SMEM128>>>(
        y, DV, Wout, DV, bout, out, DV, DV, 1.0f, 0, 0, 0);
}

// round 4
// speedup vs baseline: 3.2269x; 1.8318x over previous
#include <cuda_runtime.h>
#include <cuda_bf16.h>
#include <stdint.h>

// Problem constants
#define BV 2
#define TV 1536
#define DV 1024
#define HH 16
#define HD 64
#define SS 3072            // B*T
#define D3 3072            // 3*D

// Scratch (device globals: allocation-free per harness rules)
__device__ float g_qkv[(size_t)SS * D3];            // 37.7 MB
__device__ float g_y[(size_t)SS * DV];              // 12.6 MB

#define KC  32             // gemm k-chunk (bf16 elems)
#define ST  40             // gemm smem row stride in halves
#define ST2 80             // ... bytes
#define FST  72            // flash smem row stride in halves (64 + 8 pad)
#define FST2 144           // ... bytes

// ---------------------------------------------------------------------------
__device__ __forceinline__ uint32_t smem_u32(const void* p) {
    uint32_t a;
    asm("{ .reg .u64 t; cvta.to.shared.u64 t, %1; cvt.u32.u64 %0, t; }"
        : "=r"(a) : "l"(p));
    return a;
}
__device__ __forceinline__ void ldsm4(uint32_t r[4], uint32_t addr) {
    asm volatile("ldmatrix.sync.aligned.m8n8.x4.shared.b16 {%0,%1,%2,%3}, [%4];"
                 : "=r"(r[0]), "=r"(r[1]), "=r"(r[2]), "=r"(r[3]) : "r"(addr));
}
__device__ __forceinline__ void ldsm4t(uint32_t r[4], uint32_t addr) {
    asm volatile("ldmatrix.sync.aligned.m8n8.x4.trans.shared.b16 {%0,%1,%2,%3}, [%4];"
                 : "=r"(r[0]), "=r"(r[1]), "=r"(r[2]), "=r"(r[3]) : "r"(addr));
}
__device__ __forceinline__ void mma16816(float c[4], const uint32_t a[4],
                                         uint32_t b0, uint32_t b1) {
    asm volatile("mma.sync.aligned.m16n8k16.row.col.f32.bf16.bf16.f32 "
                 "{%0,%1,%2,%3}, {%4,%5,%6,%7}, {%8,%9}, {%0,%1,%2,%3};"
                 : "+f"(c[0]), "+f"(c[1]), "+f"(c[2]), "+f"(c[3])
                 : "r"(a[0]), "r"(a[1]), "r"(a[2]), "r"(a[3]), "r"(b0), "r"(b1));
}
__device__ __forceinline__ uint32_t pack_bf2(float a, float b) {
    __nv_bfloat162 t = __floats2bfloat162_rn(a, b);
    return *(uint32_t*)&t;
}
__device__ __forceinline__ uint32_t pack_bf2_res(float a, float b, uint32_t hi) {
    __nv_bfloat162 h = *(__nv_bfloat162*)&hi;
    return pack_bf2(a - __bfloat162float(h.x), b - __bfloat162float(h.y));
}
// split fp32x4 -> bf16 hi/lo, store packed at half-offset hoff (stride-agnostic)
__device__ __forceinline__ void split4(char* hi, char* lo, int hoff, float4 v) {
    __nv_bfloat162 h01 = __floats2bfloat162_rn(v.x, v.y);
    __nv_bfloat162 h23 = __floats2bfloat162_rn(v.z, v.w);
    __nv_bfloat162 l01 = __floats2bfloat162_rn(v.x - __bfloat162float(h01.x),
                                               v.y - __bfloat162float(h01.y));
    __nv_bfloat162 l23 = __floats2bfloat162_rn(v.z - __bfloat162float(h23.x),
                                               v.w - __bfloat162float(h23.y));
    *(uint2*)(hi + hoff * 2) = make_uint2(*(uint32_t*)&h01, *(uint32_t*)&h23);
    *(uint2*)(lo + hoff * 2) = make_uint2(*(uint32_t*)&l01, *(uint32_t*)&l23);
}

// ===========================================================================
// HMMA split-fp32 GEMM (projections): C = alpha * A @ B^T + bias
// 128x128 tile, KC=32, 8 warps (4m x 2n). PERM_A as before.
// ===========================================================================
template <bool PERM_A>
__global__ __launch_bounds__(256, 1)
void mma_gemm(const float* __restrict__ A, int lda,
              const float* __restrict__ Bm, int ldb,
              const float* __restrict__ bias,
              float* __restrict__ C, int ldc,
              int K, float alpha)
{
    extern __shared__ char smem[];
    constexpr int NTILE  = 128;
    constexpr int NBW    = NTILE / 16;
    constexpr int ABYTES = 128 * ST2;
    constexpr int BBYTES = NTILE * ST2;
    constexpr int BUFB   = 2 * ABYTES + 2 * BBYTES;

    const int tid  = threadIdx.x;
    const int lane = tid & 31;
    const int wid  = tid >> 5;
    const int wm   = (wid & 3) * 32;
    const int wn   = (wid >> 2) * (NTILE / 2);

    const int bm = blockIdx.y * 128;
    const int bn = blockIdx.x * NTILE;
    const uint32_t sb0 = smem_u32(smem);

    const int c4 = (tid & 7) * 4;
    const float* aPtr[4];
#pragma unroll
    for (int it = 0; it < 4; it++) {
        int r = bm + (tid >> 3) + it * 32;
        if (PERM_A) r = (r % TV) * BV + (r / TV);
        aPtr[it] = A + (size_t)r * lda + c4;
    }
    const float* bPtr[4];
#pragma unroll
    for (int it = 0; it < 4; it++)
        bPtr[it] = Bm + (size_t)(bn + (tid >> 3) + it * 32) * ldb + c4;

    float acc[2][NBW][4];
#pragma unroll
    for (int i = 0; i < 2; i++)
#pragma unroll
        for (int j = 0; j < NBW; j++)
#pragma unroll
            for (int q = 0; q < 4; q++) acc[i][j][q] = 0.f;

    const int nc = K / KC;
    float4 pfA[4], pfB[4];

#pragma unroll
    for (int it = 0; it < 4; it++) pfA[it] = *(const float4*)(aPtr[it]);
#pragma unroll
    for (int it = 0; it < 4; it++) pfB[it] = *(const float4*)(bPtr[it]);
    {
        char* Ah = smem;            char* Al = smem + ABYTES;
        char* Bh = smem + 2*ABYTES; char* Bl = Bh + BBYTES;
#pragma unroll
        for (int it = 0; it < 4; it++)
            split4(Ah, Al, ((tid >> 3) + it * 32) * ST + c4, pfA[it]);
#pragma unroll
        for (int it = 0; it < 4; it++)
            split4(Bh, Bl, ((tid >> 3) + it * 32) * ST + c4, pfB[it]);
    }
    __syncthreads();

    for (int ci = 0; ci < nc; ci++) {
        const bool more = (ci + 1 < nc);
        if (more) {
            const int k0 = (ci + 1) * KC;
#pragma unroll
            for (int it = 0; it < 4; it++) pfA[it] = *(const float4*)(aPtr[it] + k0);
#pragma unroll
            for (int it = 0; it < 4; it++) pfB[it] = *(const float4*)(bPtr[it] + k0);
        }
        {
            const uint32_t sb  = sb0 + (ci & 1) * BUFB;
            const uint32_t sAh = sb, sAl = sb + ABYTES;
            const uint32_t sBh = sb + 2 * ABYTES, sBl = sBh + BBYTES;
            const int arow  = wm + (lane & 15);
            const int nrow0 = wn + (lane & 7) + ((lane >> 4) << 3);
            const int kbB = ((lane >> 3) & 1) * 8;
            const int kbA = (lane >> 4) * 8;
#pragma unroll
            for (int kk = 0; kk < KC; kk += 16) {
                uint32_t ah[2][4], al[2][4];
                const uint32_t aoff = arow * ST2 + (kk + kbA) * 2;
                ldsm4(ah[0], sAh + aoff);
                ldsm4(ah[1], sAh + aoff + 16 * ST2);
                ldsm4(al[0], sAl + aoff);
                ldsm4(al[1], sAl + aoff + 16 * ST2);
#pragma unroll
                for (int p = 0; p < NBW / 2; p++) {
                    uint32_t bh[4], bl[4];
                    const uint32_t boff = (nrow0 + p * 16) * ST2 + (kk + kbB) * 2;
                    ldsm4(bh, sBh + boff);
                    ldsm4(bl, sBl + boff);
#pragma unroll
                    for (int fm = 0; fm < 2; fm++) {
                        mma16816(acc[fm][2*p  ], ah[fm], bh[0], bh[1]);
                        mma16816(acc[fm][2*p  ], ah[fm], bl[0], bl[1]);
                        mma16816(acc[fm][2*p  ], al[fm], bh[0], bh[1]);
                        mma16816(acc[fm][2*p+1], ah[fm], bh[2], bh[3]);
                        mma16816(acc[fm][2*p+1], ah[fm], bl[2], bl[3]);
                        mma16816(acc[fm][2*p+1], al[fm], bh[2], bh[3]);
                    }
                }
            }
        }
        if (more) {
            char* base = smem + ((ci + 1) & 1) * BUFB;
            char* Ah = base;            char* Al = base + ABYTES;
            char* Bh = base + 2*ABYTES; char* Bl = Bh + BBYTES;
#pragma unroll
            for (int it = 0; it < 4; it++)
                split4(Ah, Al, ((tid >> 3) + it * 32) * ST + c4, pfA[it]);
#pragma unroll
            for (int it = 0; it < 4; it++)
                split4(Bh, Bl, ((tid >> 3) + it * 32) * ST + c4, pfB[it]);
        }
        __syncthreads();
    }

#pragma unroll
    for (int fm = 0; fm < 2; fm++) {
#pragma unroll
        for (int nb = 0; nb < NBW; nb++) {
            const int row = bm + wm + fm * 16 + (lane >> 2);
            const int col = bn + wn + nb * 8 + (lane & 3) * 2;
            float b0 = 0.f, b1 = 0.f;
            if (bias) { b0 = bias[col]; b1 = bias[col + 1]; }
            *(float2*)(C + (size_t)row * ldc + col) =
                make_float2(alpha * acc[fm][nb][0] + b0, alpha * acc[fm][nb][1] + b1);
            *(float2*)(C + (size_t)(row + 8) * ldc + col) =
                make_float2(alpha * acc[fm][nb][2] + b0, alpha * acc[fm][nb][3] + b1);
        }
    }
}

// ===========================================================================
// Fused flash attention: per CTA = (q-tile of 128 rows, head h).
// 8 warps, each owns 16 q-rows. Online softmax; split-bf16 HMMA for both
// QK^T and PV. Reads g_qkv, writes g_y[s][h*64+d].
// ===========================================================================
__global__ __launch_bounds__(256, 1)
void flash_attn(const float* __restrict__ qkv, float* __restrict__ y)
{
    extern __shared__ char smem[];
    const int h  = blockIdx.y;
    const int q0 = blockIdx.x * 128;
    const int tid = threadIdx.x, lane = tid & 31, wid = tid >> 5;

    constexpr int TB = 128 * FST2;   // one 128x64 bf16 tile
    char* Qh = smem;          char* Ql = Qh + TB;
    char* Kh = Ql + TB;       char* Kl = Kh + TB;
    char* Vh = Kl + TB;       char* Vl = Vh + TB;
    const uint32_t sQh = smem_u32(Qh), sQl = sQh + TB;
    const uint32_t sKh = sQl + TB, sKl = sKh + TB;
    const uint32_t sVh = sKl + TB, sVl = sVh + TB;

    const float* Qg = qkv + (size_t)q0 * D3 + h * HD;
    const float* Kg = qkv + DV + h * HD;
    const float* Vg = qkv + 2 * DV + h * HD;

    const int r16 = tid >> 4;          // 0..15
    const int c4  = (tid & 15) * 4;    // 0..60

    // stage Q once
#pragma unroll
    for (int it = 0; it < 8; it++) {
        int r = r16 + it * 16;
        split4(Qh, Ql, r * FST + c4, *(const float4*)(Qg + (size_t)r * D3 + c4));
    }
    __syncthreads();

    // preload Q fragments (A operand, 16 rows x 64 k)
    uint32_t qh[4][4], ql[4][4];
    {
        const int arow = wid * 16 + (lane & 15);
        const int kbA  = (lane >> 4) * 8;
#pragma unroll
        for (int ks = 0; ks < 4; ks++) {
            uint32_t off = arow * FST2 + (ks * 16 + kbA) * 2;
            ldsm4(qh[ks], sQh + off);
            ldsm4(ql[ks], sQl + off);
        }
    }

    float accY[8][4];
#pragma unroll
    for (int i = 0; i < 8; i++)
#pragma unroll
        for (int j = 0; j < 4; j++) accY[i][j] = 0.f;
    float m0 = -1e30f, m1 = -1e30f, l0 = 0.f, l1 = 0.f;

    const float cs = 0.125f * 1.4426950408889634f;   // 1/8 * log2(e)
    const int nrow = (lane & 7) + ((lane >> 4) << 3);
    const int kbB  = ((lane >> 3) & 1) * 8;
    const int trow = (lane & 15);
    const int dbas = ((lane >> 4) << 3);

    for (int kv = 0; kv < SS / 128; kv++) {
        const float* Kt = Kg + (size_t)(kv * 128) * D3;
        const float* Vt = Vg + (size_t)(kv * 128) * D3;
        __syncthreads();   // prev iter's ldsm reads done before overwrite
#pragma unroll
        for (int it = 0; it < 8; it++) {
            int r = r16 + it * 16;
            split4(Kh, Kl, r * FST + c4, *(const float4*)(Kt + (size_t)r * D3 + c4));
            split4(Vh, Vl, r * FST + c4, *(const float4*)(Vt + (size_t)r * D3 + c4));
        }
        __syncthreads();

        // ---- S = Q K^T (warp: 16 x 128), 3-term split ----
        float accS[16][4];
#pragma unroll
        for (int i = 0; i < 16; i++)
#pragma unroll
            for (int j = 0; j < 4; j++) accS[i][j] = 0.f;
#pragma unroll
        for (int ks = 0; ks < 4; ks++) {
#pragma unroll
            for (int g = 0; g < 8; g++) {
                uint32_t bh[4], bl[4];
                uint32_t boff = (g * 16 + nrow) * FST2 + (ks * 16 + kbB) * 2;
                ldsm4(bh, sKh + boff);
                ldsm4(bl, sKl + boff);
                mma16816(accS[2*g  ], qh[ks], bh[0], bh[1]);
                mma16816(accS[2*g  ], qh[ks], bl[0], bl[1]);
                mma16816(accS[2*g  ], ql[ks], bh[0], bh[1]);
                mma16816(accS[2*g+1], qh[ks], bh[2], bh[3]);
                mma16816(accS[2*g+1], qh[ks], bl[2], bl[3]);
                mma16816(accS[2*g+1], ql[ks], bh[2], bh[3]);
            }
        }

        // ---- online softmax (rows r=lane>>2 and r+8) ----
        float mc0 = -1e30f, mc1 = -1e30f;
#pragma unroll
        for (int nb = 0; nb < 16; nb++) {
            accS[nb][0] *= cs; accS[nb][1] *= cs;
            accS[nb][2] *= cs; accS[nb][3] *= cs;
            mc0 = fmaxf(mc0, fmaxf(accS[nb][0], accS[nb][1]));
            mc1 = fmaxf(mc1, fmaxf(accS[nb][2], accS[nb][3]));
        }
        mc0 = fmaxf(mc0, __shfl_xor_sync(~0u, mc0, 1));
        mc0 = fmaxf(mc0, __shfl_xor_sync(~0u, mc0, 2));
        mc1 = fmaxf(mc1, __shfl_xor_sync(~0u, mc1, 1));
        mc1 = fmaxf(mc1, __shfl_xor_sync(~0u, mc1, 2));
        const float mn0 = fmaxf(m0, mc0), mn1 = fmaxf(m1, mc1);
        const float f0 = exp2f(m0 - mn0), f1 = exp2f(m1 - mn1);
        m0 = mn0; m1 = mn1;

        float s0 = 0.f, s1 = 0.f;
#pragma unroll
        for (int nb = 0; nb < 16; nb++) {
            accS[nb][0] = exp2f(accS[nb][0] - mn0);
            accS[nb][1] = exp2f(accS[nb][1] - mn0);
            accS[nb][2] = exp2f(accS[nb][2] - mn1);
            accS[nb][3] = exp2f(accS[nb][3] - mn1);
            s0 += accS[nb][0] + accS[nb][1];
            s1 += accS[nb][2] + accS[nb][3];
        }
        s0 += __shfl_xor_sync(~0u, s0, 1); s0 += __shfl_xor_sync(~0u, s0, 2);
        s1 += __shfl_xor_sync(~0u, s1, 1); s1 += __shfl_xor_sync(~0u, s1, 2);
        l0 = l0 * f0 + s0;
        l1 = l1 * f1 + s1;
#pragma unroll
        for (int db = 0; db < 8; db++) {
            accY[db][0] *= f0; accY[db][1] *= f0;
            accY[db][2] *= f1; accY[db][3] *= f1;
        }

        // ---- PV: accY += P V (P from accS fragments; 3-term split) ----
#pragma unroll
        for (int ks = 0; ks < 8; ks++) {
            uint32_t ph[4], pl[4];
            ph[0] = pack_bf2(accS[2*ks  ][0], accS[2*ks  ][1]);
            ph[1] = pack_bf2(accS[2*ks  ][2], accS[2*ks  ][3]);
            ph[2] = pack_bf2(accS[2*ks+1][0], accS[2*ks+1][1]);
            ph[3] = pack_bf2(accS[2*ks+1][2], accS[2*ks+1][3]);
            pl[0] = pack_bf2_res(accS[2*ks  ][0], accS[2*ks  ][1], ph[0]);
            pl[1] = pack_bf2_res(accS[2*ks  ][2], accS[2*ks  ][3], ph[1]);
            pl[2] = pack_bf2_res(accS[2*ks+1][0], accS[2*ks+1][1], ph[2]);
            pl[3] = pack_bf2_res(accS[2*ks+1][2], accS[2*ks+1][3], ph[3]);
            const int tr = ks * 16 + trow;
#pragma unroll
            for (int g = 0; g < 4; g++) {
                uint32_t vh[4], vl[4];
                uint32_t voff = tr * FST2 + (g * 16 + dbas) * 2;
                ldsm4t(vh, sVh + voff);
                ldsm4t(vl, sVl + voff);
                mma16816(accY[2*g  ], ph, vh[0], vh[1]);
                mma16816(accY[2*g  ], ph, vl[0], vl[1]);
                mma16816(accY[2*g  ], pl, vh[0], vh[1]);
                mma16816(accY[2*g+1], ph, vh[2], vh[3]);
                mma16816(accY[2*g+1], ph, vl[2], vl[3]);
                mma16816(accY[2*g+1], pl, vh[2], vh[3]);
            }
        }
    }

    // ---- normalize + store ----
    const float il0 = 1.0f / l0, il1 = 1.0f / l1;
    const int row = q0 + wid * 16 + (lane >> 2);
#pragma unroll
    for (int db = 0; db < 8; db++) {
        const int col = h * HD + db * 8 + (lane & 3) * 2;
        *(float2*)(y + (size_t)row * DV + col) =
            make_float2(accY[db][0] * il0, accY[db][1] * il0);
        *(float2*)(y + (size_t)(row + 8) * DV + col) =
            make_float2(accY[db][2] * il1, accY[db][3] * il1);
    }
}

// ---------------------------------------------------------------------------
extern "C" void kernel_launch(void* const* d_in, const int* in_sizes, int n_in,
                              void* d_out, int out_size)
{
    const float* x    = (const float*)d_in[0];
    const float* Wqkv = (const float*)d_in[1];
    const float* bqkv = (const float*)d_in[2];
    const float* Wout = (const float*)d_in[3];
    const float* bout = (const float*)d_in[4];
    float* out = (float*)d_out;

    float* qkv; cudaGetSymbolAddress((void**)&qkv, g_qkv);
    float* y;   cudaGetSymbolAddress((void**)&y,   g_y);

    constexpr int SMEM_G = 2 * (2 * 128 * ST2 + 2 * 128 * ST2);  // 81920
    constexpr int SMEM_F = 6 * 128 * FST2;                        // 110592

    cudaFuncSetAttribute(mma_gemm<false>,
                         cudaFuncAttributeMaxDynamicSharedMemorySize, SMEM_G);
    cudaFuncSetAttribute(mma_gemm<true>,
                         cudaFuncAttributeMaxDynamicSharedMemorySize, SMEM_G);
    cudaFuncSetAttribute(flash_attn,
                         cudaFuncAttributeMaxDynamicSharedMemorySize, SMEM_F);

    // 1) qkv = x @ Wqkv^T + bqkv                [S, 3D]
    mma_gemm<false><<<dim3(D3 / 128, SS / 128), 256, SMEM_G>>>(
        x, DV, Wqkv, DV, bqkv, qkv, D3, DV, 1.0f);

    // 2) fused attention -> y[s][h*64+d]
    flash_attn<<<dim3(SS / 128, HH), 256, SMEM_F>>>(qkv, y);

    // 3) out[b*T+t] = y[t*B+b] @ Wout^T + bout  (permute folded into A reads)
    mma_gemm<true><<<dim3(DV / 128, SS / 128), 256, SMEM_G>>>(
        y, DV, Wout, DV, bout, out, DV, DV, 1.0f);
}